// round 3
// baseline (speedup 1.0000x reference)
#include <cuda_runtime.h>

// Problem constants (fixed by reference: b=2, c=512, h=w=64)
namespace {
constexpr int Bb  = 2;
constexpr int C   = 512;
constexpr int Nn  = 4096;           // h*w
constexpr int G   = 32;
constexpr int CPG = C / G;          // 16 channels per group
constexpr float EPS   = 1e-6f;
constexpr float SCALE = 0.044194173824159216f;  // 512^-0.5
}

// Scratch (allocation-free: device globals)
__device__ float g_hn[(size_t)Bb * C * Nn];              // 16 MB
__device__ float g_qkv[(size_t)Bb * 3 * C * Nn];         // 48 MB
__device__ float g_scores[(size_t)Bb * Nn * Nn];         // 134 MB
__device__ float g_av[(size_t)Bb * C * Nn];              // 16 MB

// ---------------------------------------------------------------------------
// GroupNorm: one block per (batch, group). Group slab = 16 ch * 4096 = 65536
// contiguous floats. Two passes over the slab (2nd pass hits L2).
// ---------------------------------------------------------------------------
__global__ __launch_bounds__(1024) void groupnorm_kernel(
    const float* __restrict__ x, const float* __restrict__ gamma,
    const float* __restrict__ beta, float* __restrict__ hn)
{
    int bg = blockIdx.x;
    int b = bg / G, g = bg % G;
    const size_t base = ((size_t)b * C + (size_t)g * CPG) * Nn;
    const int M = CPG * Nn;          // 65536
    const float4* x4 = (const float4*)(x + base);
    float4* o4 = (float4*)(hn + base);

    float s = 0.f, ss = 0.f;
    for (int i = threadIdx.x; i < M / 4; i += blockDim.x) {
        float4 v = x4[i];
        s  += v.x + v.y + v.z + v.w;
        ss += v.x * v.x + v.y * v.y + v.z * v.z + v.w * v.w;
    }
    __shared__ float sh_s[32], sh_ss[32];
    #pragma unroll
    for (int o = 16; o; o >>= 1) {
        s  += __shfl_xor_sync(~0u, s, o);
        ss += __shfl_xor_sync(~0u, ss, o);
    }
    int w = threadIdx.x >> 5, l = threadIdx.x & 31;
    if (l == 0) { sh_s[w] = s; sh_ss[w] = ss; }
    __syncthreads();
    int nw = blockDim.x >> 5;
    s = 0.f; ss = 0.f;
    #pragma unroll
    for (int i = 0; i < 32; i++) {
        if (i < nw) { s += sh_s[i]; ss += sh_ss[i]; }
    }
    float mean = s / (float)M;
    float var  = ss / (float)M - mean * mean;
    float rstd = rsqrtf(var + EPS);

    for (int i = threadIdx.x; i < M / 4; i += blockDim.x) {
        int c = (i * 4) / Nn;        // channel within group (4096 % 4 == 0)
        float ga = gamma[g * CPG + c] * rstd;
        float be = beta[g * CPG + c];
        float4 v = x4[i];
        v.x = (v.x - mean) * ga + be;
        v.y = (v.y - mean) * ga + be;
        v.z = (v.z - mean) * ga + be;
        v.w = (v.w - mean) * ga + be;
        o4[i] = v;
    }
}

// ---------------------------------------------------------------------------
// Tiled SGEMM: C[m,n] = alpha * sum_k A(m,k) * B(k,n) (+bias[m]) (+res[m,n])
//   TA: A stored as [K, M] (A[k*M+m]); else [M, K]
//   TB: B stored as [N, K] (B[n*K+k]); else [K, N]
// 128x128x16 block, 256 threads, 8x8 microtile. All dims multiples of tile.
// Batch via blockIdx.z with per-operand strides.
// ---------------------------------------------------------------------------
template <bool TA, bool TB, bool BIAS, bool RES>
__global__ __launch_bounds__(256) void sgemm_kernel(
    const float* __restrict__ A, const float* __restrict__ Bm,
    float* __restrict__ Cm, const float* __restrict__ bias,
    const float* __restrict__ res,
    int M, int N, int K, float alpha,
    size_t sA, size_t sB, size_t sC, size_t sRes)
{
    constexpr int BM = 128, BN = 128, BK = 16;
    __shared__ float As[BK][BM + 4];
    __shared__ float Bs[BK][BN + 4];

    int bz = blockIdx.z;
    A  += (size_t)bz * sA;
    Bm += (size_t)bz * sB;
    Cm += (size_t)bz * sC;
    if (RES) res += (size_t)bz * sRes;

    const int m0 = blockIdx.y * BM, n0 = blockIdx.x * BN;
    const int tid = threadIdx.x;
    const int tx = tid % 16, ty = tid / 16;

    float acc[8][8];
    #pragma unroll
    for (int i = 0; i < 8; i++)
        #pragma unroll
        for (int j = 0; j < 8; j++) acc[i][j] = 0.f;

    for (int k0 = 0; k0 < K; k0 += BK) {
        #pragma unroll
        for (int it = 0; it < (BM * BK) / 256; ++it) {
            int idx = tid + it * 256;
            int m, k;
            if (TA) { k = idx / BM; m = idx % BM; }
            else    { m = idx / BK; k = idx % BK; }
            As[k][m] = TA ? A[(size_t)(k0 + k) * M + (m0 + m)]
                          : A[(size_t)(m0 + m) * K + (k0 + k)];
        }
        #pragma unroll
        for (int it = 0; it < (BN * BK) / 256; ++it) {
            int idx = tid + it * 256;
            int n, k;
            if (TB) { n = idx / BK; k = idx % BK; }
            else    { k = idx / BN; n = idx % BN; }
            Bs[k][n] = TB ? Bm[(size_t)(n0 + n) * K + (k0 + k)]
                          : Bm[(size_t)(k0 + k) * N + (n0 + n)];
        }
        __syncthreads();
        #pragma unroll
        for (int k = 0; k < BK; ++k) {
            float a[8], bf[8];
            #pragma unroll
            for (int i = 0; i < 8; i++) a[i]  = As[k][ty * 8 + i];
            #pragma unroll
            for (int j = 0; j < 8; j++) bf[j] = Bs[k][tx * 8 + j];
            #pragma unroll
            for (int i = 0; i < 8; i++)
                #pragma unroll
                for (int j = 0; j < 8; j++)
                    acc[i][j] += a[i] * bf[j];
        }
        __syncthreads();
    }

    #pragma unroll
    for (int i = 0; i < 8; i++) {
        int m = m0 + ty * 8 + i;
        float bv = BIAS ? bias[m] : 0.f;
        #pragma unroll
        for (int j4 = 0; j4 < 2; j4++) {
            int n = n0 + tx * 8 + j4 * 4;
            float4 v;
            v.x = acc[i][j4 * 4 + 0] * alpha + bv;
            v.y = acc[i][j4 * 4 + 1] * alpha + bv;
            v.z = acc[i][j4 * 4 + 2] * alpha + bv;
            v.w = acc[i][j4 * 4 + 3] * alpha + bv;
            if (RES) {
                float4 r = *(const float4*)&res[(size_t)m * N + n];
                v.x += r.x; v.y += r.y; v.z += r.z; v.w += r.w;
            }
            *(float4*)&Cm[(size_t)m * N + n] = v;
        }
    }
}

// ---------------------------------------------------------------------------
// Row softmax over 4096, one block/row, row register-resident (16 f/thread)
// ---------------------------------------------------------------------------
__global__ __launch_bounds__(256) void softmax_kernel(float* __restrict__ scores)
{
    float4* p4 = (float4*)(scores + (size_t)blockIdx.x * Nn);
    __shared__ float sh[8];
    int tid = threadIdx.x;
    float4 v[4];
    float mx = -3.4e38f;
    #pragma unroll
    for (int i = 0; i < 4; i++) {
        v[i] = p4[tid + i * 256];
        mx = fmaxf(mx, fmaxf(fmaxf(v[i].x, v[i].y), fmaxf(v[i].z, v[i].w)));
    }
    #pragma unroll
    for (int o = 16; o; o >>= 1) mx = fmaxf(mx, __shfl_xor_sync(~0u, mx, o));
    if ((tid & 31) == 0) sh[tid >> 5] = mx;
    __syncthreads();
    mx = sh[0];
    #pragma unroll
    for (int w = 1; w < 8; w++) mx = fmaxf(mx, sh[w]);

    float sum = 0.f;
    #pragma unroll
    for (int i = 0; i < 4; i++) {
        v[i].x = __expf(v[i].x - mx); v[i].y = __expf(v[i].y - mx);
        v[i].z = __expf(v[i].z - mx); v[i].w = __expf(v[i].w - mx);
        sum += v[i].x + v[i].y + v[i].z + v[i].w;
    }
    #pragma unroll
    for (int o = 16; o; o >>= 1) sum += __shfl_xor_sync(~0u, sum, o);
    __syncthreads();                      // done reading sh (max phase)
    if ((tid & 31) == 0) sh[tid >> 5] = sum;
    __syncthreads();
    sum = 0.f;
    #pragma unroll
    for (int w = 0; w < 8; w++) sum += sh[w];
    float inv = 1.f / sum;
    #pragma unroll
    for (int i = 0; i < 4; i++) {
        v[i].x *= inv; v[i].y *= inv; v[i].z *= inv; v[i].w *= inv;
        p4[tid + i * 256] = v[i];
    }
}

// ---------------------------------------------------------------------------
extern "C" void kernel_launch(void* const* d_in, const int* in_sizes, int n_in,
                              void* d_out, int out_size)
{
    const float* x      = (const float*)d_in[0];
    const float* gamma  = (const float*)d_in[1];
    const float* beta   = (const float*)d_in[2];
    const float* qkv_w  = (const float*)d_in[3];
    const float* qkv_b  = (const float*)d_in[4];
    const float* proj_w = (const float*)d_in[5];
    const float* proj_b = (const float*)d_in[6];
    float* out = (float*)d_out;

    float *hn, *qkv, *scores, *av;
    cudaGetSymbolAddress((void**)&hn, g_hn);
    cudaGetSymbolAddress((void**)&qkv, g_qkv);
    cudaGetSymbolAddress((void**)&scores, g_scores);
    cudaGetSymbolAddress((void**)&av, g_av);

    const size_t sCN  = (size_t)C * Nn;       // per-batch stride, [C, N] buffers
    const size_t s3CN = (size_t)3 * C * Nn;   // qkv per-batch stride
    const size_t sNN  = (size_t)Nn * Nn;      // scores per-batch stride

    // 1) GroupNorm -> g_hn [b, C, N]
    groupnorm_kernel<<<Bb * G, 1024>>>(x, gamma, beta, hn);

    // 2) QKV GEMM: qkv[b, 3C, N] = qkv_w[3C, C] @ hn[b, C, N] + qkv_b
    {
        dim3 grid(Nn / 128, (3 * C) / 128, Bb);
        sgemm_kernel<false, false, true, false><<<grid, 256>>>(
            qkv_w, hn, qkv, qkv_b, nullptr,
            3 * C, Nn, C, 1.f, 0, sCN, s3CN, 0);
    }

    // 3) scores[b, n, m] = SCALE * q[b,:,n]^T k[b,:,m]   (TA: q is [C, N])
    {
        dim3 grid(Nn / 128, Nn / 128, Bb);
        sgemm_kernel<true, false, false, false><<<grid, 256>>>(
            qkv /*q*/, qkv + sCN /*k*/, scores, nullptr, nullptr,
            Nn, Nn, C, SCALE, s3CN, s3CN, sNN, 0);
    }

    // 4) softmax over last axis
    softmax_kernel<<<Bb * Nn, 256>>>(scores);

    // 5) av[b, c, n] = sum_m v[b,c,m] * attn[b,n,m]   (TB: attn is [N, K=m])
    {
        dim3 grid(Nn / 128, C / 128, Bb);
        sgemm_kernel<false, true, false, false><<<grid, 256>>>(
            qkv + 2 * sCN /*v*/, scores, av, nullptr, nullptr,
            C, Nn, Nn, 1.f, s3CN, sNN, sCN, 0);
    }

    // 6) out = proj_w @ av + proj_b + x
    {
        dim3 grid(Nn / 128, C / 128, Bb);
        sgemm_kernel<false, false, true, true><<<grid, 256>>>(
            proj_w, av, out, proj_b, x,
            C, Nn, C, 1.f, 0, sCN, sCN, sCN);
    }
}

// round 6
// speedup vs baseline: 4.1873x; 4.1873x over previous
#include <cuda_runtime.h>
#include <cstdint>

// ---------------------------------------------------------------------------
// Problem constants (b=2, c=512, h=w=64)
// ---------------------------------------------------------------------------
namespace {
constexpr int Bb  = 2;
constexpr int C   = 512;
constexpr int Nn  = 4096;
constexpr int G   = 32;
constexpr int CPG = C / G;          // 16
constexpr float EPS   = 1e-6f;
constexpr float SCALE = 0.044194173824159216f;  // 512^-0.5

// GEMM tiling
constexpr int BM = 128, BN = 128, BK = 16;
constexpr int LDS_PAD = 20;                      // floats per smem row (pad 4)
constexpr int STAGE_U32 = BM * LDS_PAD;          // per-matrix per-stage u32s
// smem: As[2][STAGE] ++ Bs[2][STAGE]
constexpr int SMEM_BYTES = 4 * STAGE_U32 * 4;    // 40960
}

// Scratch (allocation-free device globals)
__device__ float g_hnT[(size_t)Bb * Nn * C];          // [b, n, c]
__device__ float g_qkvT[(size_t)Bb * Nn * 3 * C];     // [b, n, 3c]
__device__ float g_vT[(size_t)Bb * C * Nn];           // [b, c, m]
__device__ float g_scores[(size_t)Bb * Nn * Nn];      // [b, n, m]
__device__ float g_avT[(size_t)Bb * Nn * C];          // [b, n, c]

__device__ __forceinline__ uint32_t f2tf32(float f) {
    uint32_t u;
    asm("cvt.rna.tf32.f32 %0, %1;" : "=r"(u) : "f"(f));
    return u;
}

__device__ __forceinline__ void mma_tf32(float* d, const uint32_t* a,
                                         const uint32_t* b) {
    asm volatile(
        "mma.sync.aligned.m16n8k8.row.col.f32.tf32.tf32.f32 "
        "{%0,%1,%2,%3}, {%4,%5,%6,%7}, {%8,%9}, {%0,%1,%2,%3};"
        : "+f"(d[0]), "+f"(d[1]), "+f"(d[2]), "+f"(d[3])
        : "r"(a[0]), "r"(a[1]), "r"(a[2]), "r"(a[3]), "r"(b[0]), "r"(b[1]));
}

// ---------------------------------------------------------------------------
// GroupNorm -> token-major hnT[b, n, c]
// ---------------------------------------------------------------------------
__global__ __launch_bounds__(1024) void groupnorm_kernel(
    const float* __restrict__ x, const float* __restrict__ gamma,
    const float* __restrict__ beta, float* __restrict__ hnT)
{
    int bg = blockIdx.x;
    int b = bg / G, g = bg % G;
    const size_t base = ((size_t)b * C + (size_t)g * CPG) * Nn;
    const int M = CPG * Nn;
    const float4* x4 = (const float4*)(x + base);
    float* outb = hnT + (size_t)b * Nn * C;

    float s = 0.f, ss = 0.f;
    for (int i = threadIdx.x; i < M / 4; i += blockDim.x) {
        float4 v = x4[i];
        s  += v.x + v.y + v.z + v.w;
        ss += v.x * v.x + v.y * v.y + v.z * v.z + v.w * v.w;
    }
    __shared__ float sh_s[32], sh_ss[32];
    #pragma unroll
    for (int o = 16; o; o >>= 1) {
        s  += __shfl_xor_sync(~0u, s, o);
        ss += __shfl_xor_sync(~0u, ss, o);
    }
    int w = threadIdx.x >> 5, l = threadIdx.x & 31;
    if (l == 0) { sh_s[w] = s; sh_ss[w] = ss; }
    __syncthreads();
    s = 0.f; ss = 0.f;
    #pragma unroll
    for (int i = 0; i < 32; i++) { s += sh_s[i]; ss += sh_ss[i]; }
    float mean = s / (float)M;
    float var  = ss / (float)M - mean * mean;
    float rstd = rsqrtf(var + EPS);

    for (int i = threadIdx.x; i < M / 4; i += blockDim.x) {
        int e = i * 4;
        int c = e / Nn;
        int n = e % Nn;
        int cg = g * CPG + c;
        float ga = gamma[cg] * rstd;
        float be = beta[cg];
        float4 v = x4[i];
        outb[(size_t)(n + 0) * C + cg] = (v.x - mean) * ga + be;
        outb[(size_t)(n + 1) * C + cg] = (v.y - mean) * ga + be;
        outb[(size_t)(n + 2) * C + cg] = (v.z - mean) * ga + be;
        outb[(size_t)(n + 3) * C + cg] = (v.w - mean) * ga + be;
    }
}

// ---------------------------------------------------------------------------
// v transpose: vT[b, c, m] = qkvT[b, m, 2C + c]
// ---------------------------------------------------------------------------
__global__ __launch_bounds__(256) void transpose_v_kernel(
    const float* __restrict__ qkvT, float* __restrict__ vT)
{
    __shared__ float t[32][33];
    int b = blockIdx.z;
    int m0 = blockIdx.x * 32, c0 = blockIdx.y * 32;
    const float* src = qkvT + (size_t)b * Nn * 3 * C + 2 * C;
    float* dst = vT + (size_t)b * C * Nn;
    int tx = threadIdx.x & 31, ty = threadIdx.x >> 5;
    #pragma unroll
    for (int i = 0; i < 32; i += 8)
        t[ty + i][tx] = src[(size_t)(m0 + ty + i) * (3 * C) + c0 + tx];
    __syncthreads();
    #pragma unroll
    for (int i = 0; i < 32; i += 8)
        dst[(size_t)(c0 + ty + i) * Nn + m0 + tx] = t[tx][ty + i];
}

// ---------------------------------------------------------------------------
// Row softmax over 4096 (in place)
// ---------------------------------------------------------------------------
__global__ __launch_bounds__(256) void softmax_kernel(float* __restrict__ scores)
{
    float4* p4 = (float4*)(scores + (size_t)blockIdx.x * Nn);
    __shared__ float sh[8];
    int tid = threadIdx.x;
    float4 v[4];
    float mx = -3.4e38f;
    #pragma unroll
    for (int i = 0; i < 4; i++) {
        v[i] = p4[tid + i * 256];
        mx = fmaxf(mx, fmaxf(fmaxf(v[i].x, v[i].y), fmaxf(v[i].z, v[i].w)));
    }
    #pragma unroll
    for (int o = 16; o; o >>= 1) mx = fmaxf(mx, __shfl_xor_sync(~0u, mx, o));
    if ((tid & 31) == 0) sh[tid >> 5] = mx;
    __syncthreads();
    mx = sh[0];
    #pragma unroll
    for (int w = 1; w < 8; w++) mx = fmaxf(mx, sh[w]);

    float sum = 0.f;
    #pragma unroll
    for (int i = 0; i < 4; i++) {
        v[i].x = __expf(v[i].x - mx); v[i].y = __expf(v[i].y - mx);
        v[i].z = __expf(v[i].z - mx); v[i].w = __expf(v[i].w - mx);
        sum += v[i].x + v[i].y + v[i].z + v[i].w;
    }
    #pragma unroll
    for (int o = 16; o; o >>= 1) sum += __shfl_xor_sync(~0u, sum, o);
    __syncthreads();
    if ((tid & 31) == 0) sh[tid >> 5] = sum;
    __syncthreads();
    sum = 0.f;
    #pragma unroll
    for (int w = 0; w < 8; w++) sum += sh[w];
    float inv = 1.f / sum;
    #pragma unroll
    for (int i = 0; i < 4; i++) {
        v[i].x *= inv; v[i].y *= inv; v[i].z *= inv; v[i].w *= inv;
        p4[tid + i * 256] = v[i];
    }
}

// ---------------------------------------------------------------------------
// tf32 mma.sync TN GEMM: D[M,N] = alpha * A[M,K] @ B[N,K]^T (+bias) (+res)
// A,B row-major fp32 (cvt.rna -> tf32 at smem fill).
// CTA 128x128, 256 thr, 8 warps (2x4), warptile 64x32, mma m16n8k8.
// BIAS_MODE: 0 none, 1 bias[col], 2 bias[row]. RES adds res.
// ---------------------------------------------------------------------------
template <int BIAS_MODE, bool RES>
__global__ __launch_bounds__(256, 1) void tc_gemm(
    const float* __restrict__ A, const float* __restrict__ B,
    float* __restrict__ Cm, const float* __restrict__ bias,
    const float* __restrict__ res,
    int M, int N, int K, int lda, int ldb, int ldc, float alpha,
    size_t sA, size_t sB, size_t sC, size_t sRes)
{
    extern __shared__ uint32_t smem[];
    uint32_t* As = smem;                    // [2][STAGE_U32]
    uint32_t* Bs = smem + 2 * STAGE_U32;    // [2][STAGE_U32]

    const int tid  = threadIdx.x;
    const int lane = tid & 31;
    const int warp = tid >> 5;
    const int wr = warp >> 2;               // 0..1 -> m offset 64*wr
    const int wc = warp & 3;                // 0..3 -> n offset 32*wc
    const int bz = blockIdx.z;
    A  += (size_t)bz * sA;
    B  += (size_t)bz * sB;
    Cm += (size_t)bz * sC;
    if (RES) res += (size_t)bz * sRes;
    const int m0 = blockIdx.y * BM, n0 = blockIdx.x * BN;
    const float* Ab = A + (size_t)m0 * lda;
    const float* Bb_ = B + (size_t)n0 * ldb;

    const int KT = K / BK;
    const int lrow = tid >> 2;              // 0..63? no: 256/4 = 64 -> need 128 rows /2 iters
    const int lk4  = tid & 3;

    float acc[4][4][4];
    #pragma unroll
    for (int i = 0; i < 4; i++)
        #pragma unroll
        for (int j = 0; j < 4; j++)
            #pragma unroll
            for (int k = 0; k < 4; k++) acc[i][j][k] = 0.f;

    float4 ra[2], rb[2];
    // prologue: load stage 0
    #pragma unroll
    for (int i = 0; i < 2; i++) {
        int row = lrow + i * 64;
        ra[i] = *(const float4*)(Ab + (size_t)row * lda + lk4 * 4);
        rb[i] = *(const float4*)(Bb_ + (size_t)row * ldb + lk4 * 4);
    }
    #pragma unroll
    for (int i = 0; i < 2; i++) {
        int row = lrow + i * 64;
        uint32_t* a = As + row * LDS_PAD + lk4 * 4;
        a[0] = f2tf32(ra[i].x); a[1] = f2tf32(ra[i].y);
        a[2] = f2tf32(ra[i].z); a[3] = f2tf32(ra[i].w);
        uint32_t* b = Bs + row * LDS_PAD + lk4 * 4;
        b[0] = f2tf32(rb[i].x); b[1] = f2tf32(rb[i].y);
        b[2] = f2tf32(rb[i].z); b[3] = f2tf32(rb[i].w);
    }
    __syncthreads();

    for (int it = 0; it < KT; ++it) {
        const int cur = it & 1;
        if (it + 1 < KT) {
            const float* Ak = Ab + (it + 1) * BK;
            const float* Bk = Bb_ + (it + 1) * BK;
            #pragma unroll
            for (int i = 0; i < 2; i++) {
                int row = lrow + i * 64;
                ra[i] = *(const float4*)(Ak + (size_t)row * lda + lk4 * 4);
                rb[i] = *(const float4*)(Bk + (size_t)row * ldb + lk4 * 4);
            }
        }
        const uint32_t* Ac = As + cur * STAGE_U32;
        const uint32_t* Bc = Bs + cur * STAGE_U32;
        #pragma unroll
        for (int kk = 0; kk < 2; ++kk) {
            const int kb = kk * 8;
            uint32_t af[4][4], bf[4][2];
            #pragma unroll
            for (int mt = 0; mt < 4; ++mt) {
                int r = wr * 64 + mt * 16 + (lane >> 2);
                const uint32_t* p = Ac + r * LDS_PAD + kb + (lane & 3);
                af[mt][0] = p[0];
                af[mt][1] = p[8 * LDS_PAD];
                af[mt][2] = p[4];
                af[mt][3] = p[8 * LDS_PAD + 4];
            }
            #pragma unroll
            for (int nt = 0; nt < 4; ++nt) {
                int n = wc * 32 + nt * 8 + (lane >> 2);
                const uint32_t* p = Bc + n * LDS_PAD + kb + (lane & 3);
                bf[nt][0] = p[0];
                bf[nt][1] = p[4];
            }
            #pragma unroll
            for (int mt = 0; mt < 4; ++mt)
                #pragma unroll
                for (int nt = 0; nt < 4; ++nt)
                    mma_tf32(acc[mt][nt], af[mt], bf[nt]);
        }
        if (it + 1 < KT) {
            const int nxt = (it + 1) & 1;
            #pragma unroll
            for (int i = 0; i < 2; i++) {
                int row = lrow + i * 64;
                uint32_t* a = As + nxt * STAGE_U32 + row * LDS_PAD + lk4 * 4;
                a[0] = f2tf32(ra[i].x); a[1] = f2tf32(ra[i].y);
                a[2] = f2tf32(ra[i].z); a[3] = f2tf32(ra[i].w);
                uint32_t* b = Bs + nxt * STAGE_U32 + row * LDS_PAD + lk4 * 4;
                b[0] = f2tf32(rb[i].x); b[1] = f2tf32(rb[i].y);
                b[2] = f2tf32(rb[i].z); b[3] = f2tf32(rb[i].w);
            }
            __syncthreads();
        }
    }

    // Epilogue
    #pragma unroll
    for (int mt = 0; mt < 4; ++mt) {
        int row0 = m0 + wr * 64 + mt * 16 + (lane >> 2);
        #pragma unroll
        for (int half = 0; half < 2; ++half) {
            int m = row0 + half * 8;
            float bias_row = (BIAS_MODE == 2) ? bias[m] : 0.f;
            #pragma unroll
            for (int nt = 0; nt < 4; ++nt) {
                int col = n0 + wc * 32 + nt * 8 + 2 * (lane & 3);
                float2 v;
                v.x = acc[mt][nt][half * 2 + 0] * alpha;
                v.y = acc[mt][nt][half * 2 + 1] * alpha;
                if (BIAS_MODE == 1) { v.x += bias[col]; v.y += bias[col + 1]; }
                else if (BIAS_MODE == 2) { v.x += bias_row; v.y += bias_row; }
                if (RES) {
                    float2 rr = *(const float2*)(res + (size_t)m * ldc + col);
                    v.x += rr.x; v.y += rr.y;
                }
                *(float2*)(Cm + (size_t)m * ldc + col) = v;
            }
        }
    }
}

// ---------------------------------------------------------------------------
extern "C" void kernel_launch(void* const* d_in, const int* in_sizes, int n_in,
                              void* d_out, int out_size)
{
    const float* x      = (const float*)d_in[0];
    const float* gamma  = (const float*)d_in[1];
    const float* beta   = (const float*)d_in[2];
    const float* qkv_w  = (const float*)d_in[3];
    const float* qkv_b  = (const float*)d_in[4];
    const float* proj_w = (const float*)d_in[5];
    const float* proj_b = (const float*)d_in[6];
    float* out = (float*)d_out;

    float *hnT, *qkvT, *vT, *scores, *avT;
    cudaGetSymbolAddress((void**)&hnT, g_hnT);
    cudaGetSymbolAddress((void**)&qkvT, g_qkvT);
    cudaGetSymbolAddress((void**)&vT, g_vT);
    cudaGetSymbolAddress((void**)&scores, g_scores);
    cudaGetSymbolAddress((void**)&avT, g_avT);

    const size_t sNC  = (size_t)Nn * C;
    const size_t sN3C = (size_t)Nn * 3 * C;
    const size_t sNN  = (size_t)Nn * Nn;
    const size_t sCN  = (size_t)C * Nn;

    // 1) GroupNorm -> hnT [b, n, c]
    groupnorm_kernel<<<Bb * G, 1024>>>(x, gamma, beta, hnT);

    // 2) qkvT[b, n, o] = hnT[b, n, :] @ qkv_w[o, :]^T + qkv_b[o]
    {
        dim3 grid((3 * C) / BN, Nn / BM, Bb);
        tc_gemm<1, false><<<grid, 256, SMEM_BYTES>>>(
            hnT, qkv_w, qkvT, qkv_b, nullptr,
            Nn, 3 * C, C, C, C, 3 * C, 1.f, sNC, 0, sN3C, 0);
    }

    // 3) scores[b, n, m] = SCALE * q[n,:] . k[m,:]
    {
        dim3 grid(Nn / BN, Nn / BM, Bb);
        tc_gemm<0, false><<<grid, 256, SMEM_BYTES>>>(
            qkvT, qkvT + C, scores, nullptr, nullptr,
            Nn, Nn, C, 3 * C, 3 * C, Nn, SCALE, sN3C, sN3C, sNN, 0);
    }

    // 4) softmax rows
    softmax_kernel<<<Bb * Nn, 256>>>(scores);

    // 5) vT[b, c, m] = qkvT[b, m, 2C + c]
    {
        dim3 grid(Nn / 32, C / 32, Bb);
        transpose_v_kernel<<<grid, 256>>>(qkvT, vT);
    }

    // 6) avT[b, n, c] = attn[n, :] @ vT[c, :]^T
    {
        dim3 grid(C / BN, Nn / BM, Bb);
        tc_gemm<0, false><<<grid, 256, SMEM_BYTES>>>(
            scores, vT, avT, nullptr, nullptr,
            Nn, C, Nn, Nn, Nn, C, 1.f, sNN, sCN, sNC, 0);
    }

    // 7) out[b, c, n] = proj_w[c, :] @ avT[n, :]^T + proj_b[c] + x[b, c, n]
    {
        dim3 grid(Nn / BN, C / BM, Bb);
        tc_gemm<2, true><<<grid, 256, SMEM_BYTES>>>(
            proj_w, avT, out, proj_b, x,
            C, Nn, C, C, C, Nn, 1.f, 0, sNC, sCN, sCN);
    }
}